// round 9
// baseline (speedup 1.0000x reference)
#include <cuda_runtime.h>

// Rz_layer, fused single kernel, loads-first, 1024-thread CTAs, fast sincos.
//   out = exp(-0.5i * phase(blk, d)) * (re + i*im)
//   phase(blk, d) = sum_q w[blk][q] * (1 - 2*bit_q(d))
//   E(d) = exp(-i*phase/2) = E_hi[d>>6] * E_lo[d&63]
//   out_re = E.re*r - E.im*m ; out_im = E.re*m + E.im*r
//
// Shapes: state (256, 32, 2, 4096) fp32; weights (32, 12) fp32.
// Output: (2, 256, 32, 2, 4096) fp32 -> real plane then imag plane.
//
// Each 1024-thread CTA covers one full (batch, blk, dc) slice of 4096 d:
// full 64-entry hi + 64-entry lo factor tables built once per 4096 elements,
// one barrier per 32 warps. One float4 per thread keeps regs at 32
// (2 CTAs x 1024 = 2048 threads/SM). State loads issue before the table
// build so the MUFU sincos chain drains inside the DRAM-load shadow.
// |angle| <= 6*pi/4 < 5 -> __sincosf abs error ~2e-6, far under the 1e-3 gate.

#define NQ       12
#define DIM      4096
#define NBLOCKS  32
#define DC       2
#define BATCH    256
#define NELEM    (BATCH * NBLOCKS * DC * DIM)   // 67108864

__device__ __forceinline__ float2 cmul(float2 a, float2 b) {
    float2 r;
    r.x = fmaf(a.x, b.x, -a.y * b.y);
    r.y = fmaf(a.x, b.y,  a.y * b.x);
    return r;
}

__global__ void __launch_bounds__(1024)
rz_fused_kernel(const float*  __restrict__ w,
                const float4* __restrict__ re,
                const float4* __restrict__ im,
                float4*       __restrict__ out_re,
                float4*       __restrict__ out_im) {
    __shared__ float2 s_hi[64];   // E_hi for all 64 (d>>6) values of this slice
    __shared__ float2 s_lo[64];   // E_lo for all 64 (d&63) values

    const int tid    = threadIdx.x;              // 0..1023
    const int u_base = blockIdx.x << 10;         // first float4 index of CTA
    const int u      = u_base + tid;

    // ---- issue state loads FIRST (latency starts now) ----
    float4 r = __ldcs(&re[u]);                   // streaming, evict-first
    float4 m = __ldcs(&im[u]);

    const int blk = (blockIdx.x >> 1) & 31;      // u_base>>11 & 31; CTA-invariant

    // ---- build factor tables (128 fast sincos) under the load shadow ----
    if (tid < 64) {
        int j = tid;                             // the d>>6 value (full range)
        float angle = 0.0f;
#pragma unroll
        for (int q = 0; q < 6; q++) {
            float sign = ((j >> (5 - q)) & 1) ? -0.5f : 0.5f;
            angle = fmaf(__ldg(&w[blk * NQ + q]), sign, angle);
        }
        float s, c;
        __sincosf(angle, &s, &c);                // MUFU fast path; |angle| < 5
        s_hi[j] = make_float2(c, -s);            // exp(-i*angle)
    } else if (tid < 128) {
        int j = tid - 64;                        // the d&63 value
        float angle = 0.0f;
#pragma unroll
        for (int q = 0; q < 6; q++) {
            float sign = ((j >> (5 - q)) & 1) ? -0.5f : 0.5f;
            angle = fmaf(__ldg(&w[blk * NQ + 6 + q]), sign, angle);
        }
        float s, c;
        __sincosf(angle, &s, &c);
        s_lo[j] = make_float2(c, -s);
    }
    __syncthreads();

    // ---- per-thread rotation coefficients ----
    // d4 = tid (u_base&1023 == 0); d>>6 = tid>>4; d&63 = 4*(tid&15)
    float2 eh = s_hi[tid >> 4];
    const float4* lo4 = reinterpret_cast<const float4*>(s_lo);
    int lb = (tid & 15) << 1;
    float4 lo01 = lo4[lb];
    float4 lo23 = lo4[lb + 1];

    float2 E0 = cmul(eh, make_float2(lo01.x, lo01.y));
    float2 E1 = cmul(eh, make_float2(lo01.z, lo01.w));
    float2 E2 = cmul(eh, make_float2(lo23.x, lo23.y));
    float2 E3 = cmul(eh, make_float2(lo23.z, lo23.w));

    float4 orr, oii;
    orr.x = fmaf(E0.x, r.x, -E0.y * m.x);
    oii.x = fmaf(E0.x, m.x,  E0.y * r.x);
    orr.y = fmaf(E1.x, r.y, -E1.y * m.y);
    oii.y = fmaf(E1.x, m.y,  E1.y * r.y);
    orr.z = fmaf(E2.x, r.z, -E2.y * m.z);
    oii.z = fmaf(E2.x, m.z,  E2.y * r.z);
    orr.w = fmaf(E3.x, r.w, -E3.y * m.w);
    oii.w = fmaf(E3.x, m.w,  E3.y * r.w);

    __stcs(&out_re[u], orr);
    __stcs(&out_im[u], oii);
}

extern "C" void kernel_launch(void* const* d_in, const int* in_sizes, int n_in,
                              void* d_out, int out_size) {
    // metadata order: state_re, state_im, weights — robust to the small
    // (384-element) weights tensor landing in any slot.
    const float* sre = nullptr;
    const float* sim = nullptr;
    const float* w   = nullptr;
    for (int i = 0; i < n_in; i++) {
        if (in_sizes[i] == NBLOCKS * NQ) { w = (const float*)d_in[i]; }
        else if (!sre)                   { sre = (const float*)d_in[i]; }
        else                             { sim = (const float*)d_in[i]; }
    }

    float* out = (float*)d_out;        // [0, NELEM) real, [NELEM, 2*NELEM) imag

    const int ncta = NELEM / 4 / 1024; // 16384
    rz_fused_kernel<<<ncta, 1024>>>(w,
                                    (const float4*)sre,
                                    (const float4*)sim,
                                    (float4*)out,
                                    (float4*)(out + NELEM));
}